// round 4
// baseline (speedup 1.0000x reference)
#include <cuda_runtime.h>
#include <cstdint>

typedef unsigned long long ULL;

// ---------------- constants ----------------
constexpr int B  = 4;
constexpr int C  = 64;
constexpr int H  = 128;
constexpr int W  = 128;
constexpr int Hp = 130;
constexpr int Wp = 130;
constexpr int O  = 64;
constexpr int N9 = 9;

// fused prep-kernel block ranges
constexpr int NB_OFF = (B * H * W) / 256;   // 256 offset-conv blocks (first: longest)
constexpr int NB_PAD = B * 529;             // 2116 pad-transpose blocks
constexpr int NB_PW  = (O * C * N9 + 255) / 256;  // 144 weight blocks
constexpr int PREP_SMEM = N9 * C * N9 * 8;  // 41472 B

// ---------------- scratch (device globals; no allocs) ----------------
__device__ __align__(16) float g_xpad[B * Hp * Wp * C];   // NHWC zero-padded x0
__device__ __align__(16) ULL   g_wTn2[N9 * C * O];        // [n][c][o] -> (w, w) duplicated pair
__device__ __align__(16) int4   g_midx[B * H * W * N9];   // 4 corner element-offsets into g_xpad
__device__ __align__(16) float4 g_mw[B * H * W * N9];     // 4 bilinear weights (lt, rb, lb, rt)

// ---------------- packed f32x2 helpers ----------------
__device__ __forceinline__ ULL ffma2(ULL a, ULL b, ULL c) {
    ULL d;
    asm("fma.rn.f32x2 %0, %1, %2, %3;" : "=l"(d) : "l"(a), "l"(b), "l"(c));
    return d;
}
__device__ __forceinline__ ULL pack2(float lo, float hi) {
    ULL d;
    asm("mov.b64 %0, {%1, %2};" : "=l"(d) : "f"(lo), "f"(hi));
    return d;
}
__device__ __forceinline__ void unpack2(ULL v, float& lo, float& hi) {
    asm("mov.b64 {%0, %1}, %2;" : "=f"(lo), "=f"(hi) : "l"(v));
}

// ============================================================================
// Fused prep kernel: [0, NB_OFF) offset-conv + bilinear meta
//                    [NB_OFF, +NB_PAD) pad + NCHW->NHWC transpose of x0
//                    [.., +NB_PW) conv_w -> duplicated-pair reshuffle
// ============================================================================
__global__ void __launch_bounds__(256) k_prep(const float* __restrict__ x0,
                                              const float* __restrict__ x1,
                                              const float* __restrict__ p_w,
                                              const float* __restrict__ p_b,
                                              const float* __restrict__ conv_w) {
    extern __shared__ char dsm[];
    int t = threadIdx.x;
    int bid = blockIdx.x;

    if (bid < NB_OFF) {
        // ---------------- offset conv + metadata ----------------
        ULL* wsm = (ULL*)dsm;   // [n][c][kk] paired weights, 41472 B
        for (int e = t; e < N9 * C * N9; e += 256)
            wsm[e] = pack2(p_w[e], p_w[e + 5184]);
        __syncthreads();

        int P = bid * 256 + t;
        int b = P >> 14;
        int rem = P & 16383;
        int i = rem >> 7;
        int j = rem & 127;

        ULL acc[9];
        #pragma unroll
        for (int n = 0; n < 9; n++) acc[n] = pack2(p_b[n], p_b[n + 9]);

        const float* x1b = x1 + (b * C * H * W) + i * W + j;
        bool rok0 = (i > 0), rok2 = (i < H - 1), cok0 = (j > 0), cok2 = (j < W - 1);

        #pragma unroll 1
        for (int c = 0; c < C; c++) {
            const float* xc = x1b + c * (H * W);
            float v[9];
            #pragma unroll
            for (int di = 0; di < 3; di++) {
                bool rok = (di == 0) ? rok0 : ((di == 2) ? rok2 : true);
                const float* xr = xc + (di - 1) * W;
                v[di * 3 + 0] = (rok && cok0) ? xr[-1] : 0.f;
                v[di * 3 + 1] = rok ? xr[0] : 0.f;
                v[di * 3 + 2] = (rok && cok2) ? xr[1] : 0.f;
            }
            ULL vd[9];
            #pragma unroll
            for (int k = 0; k < 9; k++) vd[k] = pack2(v[k], v[k]);
            const ULL* wrow = &wsm[c * N9];
            #pragma unroll
            for (int n = 0; n < 9; n++) {
                const ULL* wn = wrow + n * (C * N9);
                #pragma unroll
                for (int k = 0; k < 9; k++)
                    acc[n] = ffma2(vd[k], wn[k], acc[n]);
            }
        }

        int gs = P * 9;
        int xb130 = b * 130;
        #pragma unroll
        for (int n = 0; n < 9; n++) {
            float ox, oy;
            unpack2(acc[n], ox, oy);
            float px = (float)(i + n / 3) + ox;
            float py = (float)(j + n % 3) + oy;
            float fx = floorf(px), fy = floorf(py);
            int qltx = max(min((int)fx, Hp - 1), 0);
            int qlty = max(min((int)fy, Wp - 1), 0);
            int qrbx = max(min((int)fx + 1, Hp - 1), 0);
            int qrby = max(min((int)fy + 1, Wp - 1), 0);
            float pxc = fminf(fmaxf(px, 0.f), (float)(Hp - 1));
            float pyc = fminf(fmaxf(py, 0.f), (float)(Wp - 1));
            float ax = 1.f + (float)qltx - pxc;
            float bx = 1.f - (float)qrbx + pxc;
            float ay = 1.f + (float)qlty - pyc;
            float by = 1.f - (float)qrby + pyc;
            int4 idx;
            idx.x = ((xb130 + qltx) * 130 + qlty) * 64;
            idx.y = ((xb130 + qrbx) * 130 + qrby) * 64;
            idx.z = ((xb130 + qltx) * 130 + qrby) * 64;
            idx.w = ((xb130 + qrbx) * 130 + qlty) * 64;
            float4 wv;
            wv.x = ax * ay;
            wv.y = bx * by;
            wv.z = ax * by;
            wv.w = bx * ay;
            g_midx[gs + n] = idx;
            g_mw[gs + n] = wv;
        }
    } else if (bid < NB_OFF + NB_PAD) {
        // ---------------- pad + transpose ----------------
        float (*tile)[33] = (float(*)[33])dsm;
        int bp = bid - NB_OFF;
        int b  = bp / 529;
        int p0 = (bp - b * 529) * 32;
        int tx = t & 31;
        int ty = t >> 5;

        #pragma unroll
        for (int cc = ty; cc < 64; cc += 8) {
            int p = p0 + tx;
            float v = 0.f;
            if (p < Hp * Wp) {
                int y = p / Wp, x = p - (p / Wp) * Wp;
                if (y >= 1 && y <= H && x >= 1 && x <= W)
                    v = x0[((b * C + cc) * H + (y - 1)) * W + (x - 1)];
            }
            tile[cc][tx] = v;
        }
        __syncthreads();

        int base = (b * Hp * Wp + p0) * 64;
        for (int e = t; e < 32 * 64; e += 256) {
            int pl = e >> 6, c = e & 63;
            if (p0 + pl < Hp * Wp)
                g_xpad[base + pl * 64 + c] = tile[c][pl];
        }
    } else {
        // ---------------- conv_w reshuffle ----------------
        int idx = (bid - NB_OFF - NB_PAD) * 256 + t;
        if (idx < O * C * N9) {
            int o = idx / (C * N9);
            int c = (idx / N9) % C;
            int n = idx % N9;
            float w = conv_w[idx];
            g_wTn2[(n * C + c) * O + o] = pack2(w, w);
        }
    }
}

// ============================================================================
// k_main: tap-major gather + FMA-bound reduction GEMM.
// Block = one image row: 128 pixels x 64 outputs, 128 threads.
// Per tap n: stage dup'd W (32KB), gather+blend all 64ch of 128px into a
// chunk-swizzled smem X tile, then 64-k-step GEMM with 8o x 8px (4 f32x2
// pixel pairs) per thread -> 3 B smem / FFMA2 (FMA-bound).
// ============================================================================
__global__ void __launch_bounds__(128) k_main(float* __restrict__ out) {
    extern __shared__ char dsm[];
    ULL*  ws2   = (ULL*)dsm;          // 32768 B : [k(=c)][o] duplicated pairs
    char* xoffb = dsm + 32768;        // 32768 B : [c][128 px], 16B-chunk swizzled

    int t = threadIdx.x;
    int bid = blockIdx.x;             // 512 blocks
    int i = bid & 127;
    int b = bid >> 7;
    int pixbase = (b * H + i) * W;

    int lg = t & 15;                  // gather: channel quad  | GEMM: pixel octet
    int hg = t >> 4;                  // gather: pixel 16-group| GEMM: output octet

    ULL acc[8][4];
    #pragma unroll
    for (int r = 0; r < 8; r++)
        #pragma unroll
        for (int p = 0; p < 4; p++) acc[r][p] = 0ull;

    const int4*   midx = g_midx + pixbase * 9;
    const float4* mw   = g_mw   + pixbase * 9;
    const float*  xb   = g_xpad + lg * 4;
    int swz = (lg << 1) & 31;         // store-side chunk swizzle for channel quad lg

    #pragma unroll 1
    for (int n = 0; n < 9; n++) {
        __syncthreads();   // previous GEMM readers done before overwrite

        // ---- stage duplicated W slice for tap n (32 KB) ----
        {
            const float4* wsrc = (const float4*)(g_wTn2 + n * (C * O));
            float4* wdst = (float4*)dsm;
            #pragma unroll
            for (int k = 0; k < 16; k++) wdst[t + k * 128] = wsrc[t + k * 128];
        }

        // ---- gather + blend: channels lg*4..+3, pixels hg*16..+15, in 4-px chunks ----
        #pragma unroll 1
        for (int j = 0; j < 4; j++) {
            float rr[4][4];
            #pragma unroll
            for (int jj = 0; jj < 4; jj++) {
                int pix = hg * 16 + j * 4 + jj;
                int4   id = midx[pix * 9 + n];
                float4 g  = mw[pix * 9 + n];
                float4 v0 = *(const float4*)(xb + id.x);
                float4 v1 = *(const float4*)(xb + id.y);
                float4 v2 = *(const float4*)(xb + id.z);
                float4 v3 = *(const float4*)(xb + id.w);
                rr[jj][0] = g.x * v0.x + g.y * v1.x + g.z * v2.x + g.w * v3.x;
                rr[jj][1] = g.x * v0.y + g.y * v1.y + g.z * v2.y + g.w * v3.y;
                rr[jj][2] = g.x * v0.z + g.y * v1.z + g.z * v2.z + g.w * v3.z;
                rr[jj][3] = g.x * v0.w + g.y * v1.w + g.z * v2.w + g.w * v3.w;
            }
            int chunk = (hg * 4 + j) ^ swz;   // swizzled 16B-chunk (4 px) index
            #pragma unroll
            for (int q = 0; q < 4; q++) {
                int c = lg * 4 + q;
                *(float4*)(xoffb + c * 512 + chunk * 16) =
                    make_float4(rr[0][q], rr[1][q], rr[2][q], rr[3][q]);
            }
        }
        __syncthreads();

        // ---- GEMM: acc[o = hg*8+r][px pairs of lg*8..+7] += w[o,k] * x[k,px] ----
        #pragma unroll 2
        for (int k = 0; k < 64; k++) {
            int kq = k >> 2;
            const char* xrow = xoffb + k * 512 + (((lg ^ kq) & 15) << 5);
            ulonglong2 x01 = *(const ulonglong2*)xrow;          // pixel pairs 0,1
            ulonglong2 x23 = *(const ulonglong2*)(xrow + 16);   // pixel pairs 2,3
            const ULL* wrow = ws2 + k * 64 + hg * 8;
            ulonglong2 w01 = *(const ulonglong2*)(wrow + 0);
            ulonglong2 w23 = *(const ulonglong2*)(wrow + 2);
            ulonglong2 w45 = *(const ulonglong2*)(wrow + 4);
            ulonglong2 w67 = *(const ulonglong2*)(wrow + 6);
            acc[0][0] = ffma2(x01.x, w01.x, acc[0][0]);
            acc[0][1] = ffma2(x01.y, w01.x, acc[0][1]);
            acc[0][2] = ffma2(x23.x, w01.x, acc[0][2]);
            acc[0][3] = ffma2(x23.y, w01.x, acc[0][3]);
            acc[1][0] = ffma2(x01.x, w01.y, acc[1][0]);
            acc[1][1] = ffma2(x01.y, w01.y, acc[1][1]);
            acc[1][2] = ffma2(x23.x, w01.y, acc[1][2]);
            acc[1][3] = ffma2(x23.y, w01.y, acc[1][3]);
            acc[2][0] = ffma2(x01.x, w23.x, acc[2][0]);
            acc[2][1] = ffma2(x01.y, w23.x, acc[2][1]);
            acc[2][2] = ffma2(x23.x, w23.x, acc[2][2]);
            acc[2][3] = ffma2(x23.y, w23.x, acc[2][3]);
            acc[3][0] = ffma2(x01.x, w23.y, acc[3][0]);
            acc[3][1] = ffma2(x01.y, w23.y, acc[3][1]);
            acc[3][2] = ffma2(x23.x, w23.y, acc[3][2]);
            acc[3][3] = ffma2(x23.y, w23.y, acc[3][3]);
            acc[4][0] = ffma2(x01.x, w45.x, acc[4][0]);
            acc[4][1] = ffma2(x01.y, w45.x, acc[4][1]);
            acc[4][2] = ffma2(x23.x, w45.x, acc[4][2]);
            acc[4][3] = ffma2(x23.y, w45.x, acc[4][3]);
            acc[5][0] = ffma2(x01.x, w45.y, acc[5][0]);
            acc[5][1] = ffma2(x01.y, w45.y, acc[5][1]);
            acc[5][2] = ffma2(x23.x, w45.y, acc[5][2]);
            acc[5][3] = ffma2(x23.y, w45.y, acc[5][3]);
            acc[6][0] = ffma2(x01.x, w67.x, acc[6][0]);
            acc[6][1] = ffma2(x01.y, w67.x, acc[6][1]);
            acc[6][2] = ffma2(x23.x, w67.x, acc[6][2]);
            acc[6][3] = ffma2(x23.y, w67.x, acc[6][3]);
            acc[7][0] = ffma2(x01.x, w67.y, acc[7][0]);
            acc[7][1] = ffma2(x01.y, w67.y, acc[7][1]);
            acc[7][2] = ffma2(x23.x, w67.y, acc[7][2]);
            acc[7][3] = ffma2(x23.y, w67.y, acc[7][3]);
        }
    }

    // ---- write out: o = hg*8+r, pixels lg*8..+7 ----
    float* ob = out + ((b * O + hg * 8) * H + i) * W + lg * 8;
    #pragma unroll
    for (int r = 0; r < 8; r++) {
        float4 lo4, hi4;
        unpack2(acc[r][0], lo4.x, lo4.y);
        unpack2(acc[r][1], lo4.z, lo4.w);
        unpack2(acc[r][2], hi4.x, hi4.y);
        unpack2(acc[r][3], hi4.z, hi4.w);
        *(float4*)(ob + r * (H * W))     = lo4;
        *(float4*)(ob + r * (H * W) + 4) = hi4;
    }
}

// ============================================================================
extern "C" void kernel_launch(void* const* d_in, const int* in_sizes, int n_in,
                              void* d_out, int out_size) {
    const float* x0     = (const float*)d_in[0];
    const float* x1     = (const float*)d_in[1];
    const float* p_w    = (const float*)d_in[2];
    const float* p_b    = (const float*)d_in[3];
    const float* conv_w = (const float*)d_in[4];
    float* out = (float*)d_out;

    cudaFuncSetAttribute(k_main, cudaFuncAttributeMaxDynamicSharedMemorySize, 65536);

    k_prep<<<NB_OFF + NB_PAD + NB_PW, 256, PREP_SMEM>>>(x0, x1, p_w, p_b, conv_w);
    k_main<<<B * H, 128, 65536>>>(out);
}

// round 5
// speedup vs baseline: 1.1108x; 1.1108x over previous
#include <cuda_runtime.h>
#include <cstdint>

typedef unsigned long long ULL;

// ---------------- constants ----------------
constexpr int B  = 4;
constexpr int C  = 64;
constexpr int H  = 128;
constexpr int W  = 128;
constexpr int Hp = 130;
constexpr int Wp = 130;
constexpr int O  = 64;
constexpr int N9 = 9;

// fused prep-kernel block ranges
constexpr int NB_OFF = (B * H * W) / 256;   // 256 offset-conv blocks (first: longest)
constexpr int NB_PAD = B * 529;             // 2116 pad-transpose blocks
constexpr int NB_PW  = (O * C * N9 + 255) / 256;  // 144 weight blocks
constexpr int PREP_SMEM = N9 * C * N9 * 8;  // 41472 B

// ---------------- scratch (device globals; no allocs) ----------------
__device__ __align__(16) float g_xpad[B * Hp * Wp * C];   // NHWC zero-padded x0
__device__ __align__(16) ULL   g_wTn2[N9 * C * O];        // [n][c][o] -> (w, w) duplicated pair
__device__ __align__(16) int4   g_midx[B * H * W * N9];   // 4 corner element-offsets into g_xpad
__device__ __align__(16) float4 g_mw[B * H * W * N9];     // 4 bilinear weights (lt, rb, lb, rt)

// ---------------- packed f32x2 helpers ----------------
__device__ __forceinline__ ULL ffma2(ULL a, ULL b, ULL c) {
    ULL d;
    asm("fma.rn.f32x2 %0, %1, %2, %3;" : "=l"(d) : "l"(a), "l"(b), "l"(c));
    return d;
}
__device__ __forceinline__ ULL pack2(float lo, float hi) {
    ULL d;
    asm("mov.b64 %0, {%1, %2};" : "=l"(d) : "f"(lo), "f"(hi));
    return d;
}
__device__ __forceinline__ void unpack2(ULL v, float& lo, float& hi) {
    asm("mov.b64 {%0, %1}, %2;" : "=f"(lo), "=f"(hi) : "l"(v));
}

// ============================================================================
// Fused prep kernel: [0, NB_OFF) offset-conv + bilinear meta
//                    [NB_OFF, +NB_PAD) pad + NCHW->NHWC transpose of x0
//                    [.., +NB_PW) conv_w -> duplicated-pair reshuffle
// ============================================================================
__global__ void __launch_bounds__(256) k_prep(const float* __restrict__ x0,
                                              const float* __restrict__ x1,
                                              const float* __restrict__ p_w,
                                              const float* __restrict__ p_b,
                                              const float* __restrict__ conv_w) {
    extern __shared__ char dsm[];
    int t = threadIdx.x;
    int bid = blockIdx.x;

    if (bid < NB_OFF) {
        // ---------------- offset conv + metadata ----------------
        ULL* wsm = (ULL*)dsm;   // [n][c][kk] paired weights, 41472 B
        for (int e = t; e < N9 * C * N9; e += 256)
            wsm[e] = pack2(p_w[e], p_w[e + 5184]);
        __syncthreads();

        int P = bid * 256 + t;
        int b = P >> 14;
        int rem = P & 16383;
        int i = rem >> 7;
        int j = rem & 127;

        ULL acc[9];
        #pragma unroll
        for (int n = 0; n < 9; n++) acc[n] = pack2(p_b[n], p_b[n + 9]);

        const float* x1b = x1 + (b * C * H * W) + i * W + j;
        bool rok0 = (i > 0), rok2 = (i < H - 1), cok0 = (j > 0), cok2 = (j < W - 1);

        #pragma unroll 1
        for (int c = 0; c < C; c++) {
            const float* xc = x1b + c * (H * W);
            float v[9];
            #pragma unroll
            for (int di = 0; di < 3; di++) {
                bool rok = (di == 0) ? rok0 : ((di == 2) ? rok2 : true);
                const float* xr = xc + (di - 1) * W;
                v[di * 3 + 0] = (rok && cok0) ? xr[-1] : 0.f;
                v[di * 3 + 1] = rok ? xr[0] : 0.f;
                v[di * 3 + 2] = (rok && cok2) ? xr[1] : 0.f;
            }
            ULL vd[9];
            #pragma unroll
            for (int k = 0; k < 9; k++) vd[k] = pack2(v[k], v[k]);
            const ULL* wrow = &wsm[c * N9];
            #pragma unroll
            for (int n = 0; n < 9; n++) {
                const ULL* wn = wrow + n * (C * N9);
                #pragma unroll
                for (int k = 0; k < 9; k++)
                    acc[n] = ffma2(vd[k], wn[k], acc[n]);
            }
        }

        int gs = P * 9;
        int xb130 = b * 130;
        #pragma unroll
        for (int n = 0; n < 9; n++) {
            float ox, oy;
            unpack2(acc[n], ox, oy);
            float px = (float)(i + n / 3) + ox;
            float py = (float)(j + n % 3) + oy;
            float fx = floorf(px), fy = floorf(py);
            int qltx = max(min((int)fx, Hp - 1), 0);
            int qlty = max(min((int)fy, Wp - 1), 0);
            int qrbx = max(min((int)fx + 1, Hp - 1), 0);
            int qrby = max(min((int)fy + 1, Wp - 1), 0);
            float pxc = fminf(fmaxf(px, 0.f), (float)(Hp - 1));
            float pyc = fminf(fmaxf(py, 0.f), (float)(Wp - 1));
            float ax = 1.f + (float)qltx - pxc;
            float bx = 1.f - (float)qrbx + pxc;
            float ay = 1.f + (float)qlty - pyc;
            float by = 1.f - (float)qrby + pyc;
            int4 idx;
            idx.x = ((xb130 + qltx) * 130 + qlty) * 64;
            idx.y = ((xb130 + qrbx) * 130 + qrby) * 64;
            idx.z = ((xb130 + qltx) * 130 + qrby) * 64;
            idx.w = ((xb130 + qrbx) * 130 + qlty) * 64;
            float4 wv;
            wv.x = ax * ay;
            wv.y = bx * by;
            wv.z = ax * by;
            wv.w = bx * ay;
            g_midx[gs + n] = idx;
            g_mw[gs + n] = wv;
        }
    } else if (bid < NB_OFF + NB_PAD) {
        // ---------------- pad + transpose ----------------
        float (*tile)[33] = (float(*)[33])dsm;
        int bp = bid - NB_OFF;
        int b  = bp / 529;
        int p0 = (bp - b * 529) * 32;
        int tx = t & 31;
        int ty = t >> 5;

        #pragma unroll
        for (int cc = ty; cc < 64; cc += 8) {
            int p = p0 + tx;
            float v = 0.f;
            if (p < Hp * Wp) {
                int y = p / Wp, x = p - (p / Wp) * Wp;
                if (y >= 1 && y <= H && x >= 1 && x <= W)
                    v = x0[((b * C + cc) * H + (y - 1)) * W + (x - 1)];
            }
            tile[cc][tx] = v;
        }
        __syncthreads();

        int base = (b * Hp * Wp + p0) * 64;
        for (int e = t; e < 32 * 64; e += 256) {
            int pl = e >> 6, c = e & 63;
            if (p0 + pl < Hp * Wp)
                g_xpad[base + pl * 64 + c] = tile[c][pl];
        }
    } else {
        // ---------------- conv_w reshuffle ----------------
        int idx = (bid - NB_OFF - NB_PAD) * 256 + t;
        if (idx < O * C * N9) {
            int o = idx / (C * N9);
            int c = (idx / N9) % C;
            int n = idx % N9;
            float w = conv_w[idx];
            g_wTn2[(n * C + c) * O + o] = pack2(w, w);
        }
    }
}

// ============================================================================
// k_main: tap-major gather + broadcast-W reduction GEMM.
// Block = one image row: 128 pixels x 64 outputs, 256 threads (8 warps).
// GEMM: warp -> 8-output octet over ALL 128 px; lane -> 4-pixel quad.
//   Per k-step: X read = 1 LDS.128/lane (distinct, conflict-free via XOR
//   swizzle); W read = 4x LDS.128 warp-UNIFORM (smem broadcast, ~1 cyc each).
//   16 FFMA2/lane/k-step -> crossbar <= FMA pipe: FMA-bound.
// ============================================================================
__global__ void __launch_bounds__(256, 2) k_main(float* __restrict__ out) {
    extern __shared__ char dsm[];
    ULL*  ws2   = (ULL*)dsm;          // 32768 B : [k(=c)][64 o] duplicated pairs
    char* xoffb = dsm + 32768;        // 32768 B : [c][128 px], 16B-chunk XOR-swizzled

    int t = threadIdx.x;
    int warp = t >> 5;
    int lane = t & 31;
    int bid = blockIdx.x;             // 512 blocks
    int i = bid & 127;
    int b = bid >> 7;
    int pixbase = (b * H + i) * W;

    int lg = t & 15;                  // gather: channel quad
    int hg = t >> 4;                  // gather: pixel octet group (16 groups x 8 px)

    ULL acc[8][2];
    #pragma unroll
    for (int r = 0; r < 8; r++) { acc[r][0] = 0ull; acc[r][1] = 0ull; }

    const int4*   midx = g_midx + pixbase * 9;
    const float4* mw   = g_mw   + pixbase * 9;
    const float*  xb   = g_xpad + lg * 4;
    int fsw = lg & 7;                 // store-side XOR swizzle for this channel quad

    #pragma unroll 1
    for (int n = 0; n < 9; n++) {
        __syncthreads();   // previous GEMM readers done before overwrite

        // ---- stage duplicated W slice for tap n (32 KB) ----
        {
            const float4* wsrc = (const float4*)(g_wTn2 + n * (C * O));
            float4* wdst = (float4*)dsm;
            #pragma unroll
            for (int k = 0; k < 8; k++) wdst[t + k * 256] = wsrc[t + k * 256];
        }

        // ---- gather + blend: channels lg*4..+3, pixels hg*8..+7 (two 4-px chunks) ----
        #pragma unroll 1
        for (int j = 0; j < 2; j++) {
            float rr[4][4];
            #pragma unroll
            for (int jj = 0; jj < 4; jj++) {
                int pix = hg * 8 + j * 4 + jj;
                int4   id = midx[pix * 9 + n];
                float4 g  = mw[pix * 9 + n];
                float4 v0 = *(const float4*)(xb + id.x);
                float4 v1 = *(const float4*)(xb + id.y);
                float4 v2 = *(const float4*)(xb + id.z);
                float4 v3 = *(const float4*)(xb + id.w);
                rr[jj][0] = g.x * v0.x + g.y * v1.x + g.z * v2.x + g.w * v3.x;
                rr[jj][1] = g.x * v0.y + g.y * v1.y + g.z * v2.y + g.w * v3.y;
                rr[jj][2] = g.x * v0.z + g.y * v1.z + g.z * v2.z + g.w * v3.z;
                rr[jj][3] = g.x * v0.w + g.y * v1.w + g.z * v2.w + g.w * v3.w;
            }
            int chunk = (hg * 2 + j) ^ fsw;   // XOR-swizzled 16B chunk (4 px)
            #pragma unroll
            for (int q = 0; q < 4; q++) {
                int c = lg * 4 + q;
                *(float4*)(xoffb + c * 512 + chunk * 16) =
                    make_float4(rr[0][q], rr[1][q], rr[2][q], rr[3][q]);
            }
        }
        __syncthreads();

        // ---- GEMM: acc[o = warp*8+r][4 px = lane*4..+3] += w[o,k] * x[k,px] ----
        #pragma unroll 4
        for (int k = 0; k < 64; k++) {
            ulonglong2 x01 = *(const ulonglong2*)(xoffb + k * 512 +
                                                  ((lane ^ ((k >> 2) & 7)) << 4));
            const ULL* wr = ws2 + k * 64 + warp * 8;       // warp-uniform (broadcast)
            ulonglong2 w01 = *(const ulonglong2*)(wr + 0);
            ulonglong2 w23 = *(const ulonglong2*)(wr + 2);
            ulonglong2 w45 = *(const ulonglong2*)(wr + 4);
            ulonglong2 w67 = *(const ulonglong2*)(wr + 6);
            acc[0][0] = ffma2(x01.x, w01.x, acc[0][0]);
            acc[0][1] = ffma2(x01.y, w01.x, acc[0][1]);
            acc[1][0] = ffma2(x01.x, w01.y, acc[1][0]);
            acc[1][1] = ffma2(x01.y, w01.y, acc[1][1]);
            acc[2][0] = ffma2(x01.x, w23.x, acc[2][0]);
            acc[2][1] = ffma2(x01.y, w23.x, acc[2][1]);
            acc[3][0] = ffma2(x01.x, w23.y, acc[3][0]);
            acc[3][1] = ffma2(x01.y, w23.y, acc[3][1]);
            acc[4][0] = ffma2(x01.x, w45.x, acc[4][0]);
            acc[4][1] = ffma2(x01.y, w45.x, acc[4][1]);
            acc[5][0] = ffma2(x01.x, w45.y, acc[5][0]);
            acc[5][1] = ffma2(x01.y, w45.y, acc[5][1]);
            acc[6][0] = ffma2(x01.x, w67.x, acc[6][0]);
            acc[6][1] = ffma2(x01.y, w67.x, acc[6][1]);
            acc[7][0] = ffma2(x01.x, w67.y, acc[7][0]);
            acc[7][1] = ffma2(x01.y, w67.y, acc[7][1]);
        }
    }

    // ---- write out: o = warp*8+r, pixels lane*4..+3 (coalesced) ----
    float* ob = out + ((b * O + warp * 8) * H + i) * W + lane * 4;
    #pragma unroll
    for (int r = 0; r < 8; r++) {
        float4 v;
        unpack2(acc[r][0], v.x, v.y);
        unpack2(acc[r][1], v.z, v.w);
        *(float4*)(ob + r * (H * W)) = v;
    }
}

// ============================================================================
extern "C" void kernel_launch(void* const* d_in, const int* in_sizes, int n_in,
                              void* d_out, int out_size) {
    const float* x0     = (const float*)d_in[0];
    const float* x1     = (const float*)d_in[1];
    const float* p_w    = (const float*)d_in[2];
    const float* p_b    = (const float*)d_in[3];
    const float* conv_w = (const float*)d_in[4];
    float* out = (float*)d_out;

    cudaFuncSetAttribute(k_main, cudaFuncAttributeMaxDynamicSharedMemorySize, 65536);

    k_prep<<<NB_OFF + NB_PAD + NB_PW, 256, PREP_SMEM>>>(x0, x1, p_w, p_b, conv_w);
    k_main<<<B * H, 256, 65536>>>(out);
}

// round 6
// speedup vs baseline: 1.1458x; 1.0315x over previous
#include <cuda_runtime.h>
#include <cstdint>

typedef unsigned long long ULL;

// ---------------- constants ----------------
constexpr int B  = 4;
constexpr int C  = 64;
constexpr int H  = 128;
constexpr int W  = 128;
constexpr int Hp = 130;
constexpr int Wp = 130;
constexpr int O  = 64;
constexpr int N9 = 9;
constexpr int BHW = B * H * W;   // 65536

// fused prep-kernel block ranges
constexpr int NB_OFF = BHW / 256;                 // 256 offset-conv blocks
constexpr int NB_PAD = B * 529;                   // 2116 pad-transpose blocks
constexpr int NB_PW  = (O * C * N9 + 255) / 256;  // 144 weight blocks
constexpr int PREP_SMEM = N9 * C * N9 * 8;        // 41472 B

// k_main smem layout (112 KB total, 2 blocks/SM)
constexpr int SM_W    = 0;        // 32768 : [k][64 o] duplicated pairs
constexpr int SM_X    = 32768;    // 65536 : [64 c][256 px] 16B-chunk XOR swizzled
constexpr int SM_MIDX = 98304;    // 8192  : int4  [2][256]
constexpr int SM_MW   = 106496;   // 8192  : float4[2][256]
constexpr int SM_MAIN = 114688;

// ---------------- scratch (device globals; no allocs) ----------------
__device__ __align__(16) float g_xpad[B * Hp * Wp * C];   // NHWC zero-padded x0
__device__ __align__(16) ULL   g_wTn2[N9 * C * O];        // [n][c][o] -> (w, w) pair
__device__ __align__(16) int4   g_midx[N9 * BHW];         // [n][P] corner offsets
__device__ __align__(16) float4 g_mw[N9 * BHW];           // [n][P] bilinear weights

// ---------------- packed f32x2 helpers ----------------
__device__ __forceinline__ ULL ffma2(ULL a, ULL b, ULL c) {
    ULL d;
    asm("fma.rn.f32x2 %0, %1, %2, %3;" : "=l"(d) : "l"(a), "l"(b), "l"(c));
    return d;
}
__device__ __forceinline__ ULL pack2(float lo, float hi) {
    ULL d;
    asm("mov.b64 %0, {%1, %2};" : "=l"(d) : "f"(lo), "f"(hi));
    return d;
}
__device__ __forceinline__ void unpack2(ULL v, float& lo, float& hi) {
    asm("mov.b64 {%0, %1}, %2;" : "=f"(lo), "=f"(hi) : "l"(v));
}

// ============================================================================
// Fused prep kernel (offset conv + meta | pad/transpose | weight reshuffle)
// ============================================================================
__global__ void __launch_bounds__(256) k_prep(const float* __restrict__ x0,
                                              const float* __restrict__ x1,
                                              const float* __restrict__ p_w,
                                              const float* __restrict__ p_b,
                                              const float* __restrict__ conv_w) {
    extern __shared__ char dsm[];
    int t = threadIdx.x;
    int bid = blockIdx.x;

    if (bid < NB_OFF) {
        // ---------------- offset conv + metadata ----------------
        ULL* wsm = (ULL*)dsm;   // [n][c][kk] paired weights, 41472 B
        for (int e = t; e < N9 * C * N9; e += 256)
            wsm[e] = pack2(p_w[e], p_w[e + 5184]);
        __syncthreads();

        int P = bid * 256 + t;
        int b = P >> 14;
        int rem = P & 16383;
        int i = rem >> 7;
        int j = rem & 127;

        ULL acc[9];
        #pragma unroll
        for (int n = 0; n < 9; n++) acc[n] = pack2(p_b[n], p_b[n + 9]);

        const float* x1b = x1 + (b * C * H * W) + i * W + j;
        bool rok0 = (i > 0), rok2 = (i < H - 1), cok0 = (j > 0), cok2 = (j < W - 1);

        #pragma unroll 2
        for (int c = 0; c < C; c++) {
            const float* xc = x1b + c * (H * W);
            float v[9];
            #pragma unroll
            for (int di = 0; di < 3; di++) {
                bool rok = (di == 0) ? rok0 : ((di == 2) ? rok2 : true);
                const float* xr = xc + (di - 1) * W;
                v[di * 3 + 0] = (rok && cok0) ? xr[-1] : 0.f;
                v[di * 3 + 1] = rok ? xr[0] : 0.f;
                v[di * 3 + 2] = (rok && cok2) ? xr[1] : 0.f;
            }
            ULL vd[9];
            #pragma unroll
            for (int k = 0; k < 9; k++) vd[k] = pack2(v[k], v[k]);
            const ULL* wrow = &wsm[c * N9];
            #pragma unroll
            for (int n = 0; n < 9; n++) {
                const ULL* wn = wrow + n * (C * N9);
                #pragma unroll
                for (int k = 0; k < 9; k++)
                    acc[n] = ffma2(vd[k], wn[k], acc[n]);
            }
        }

        int xb130 = b * 130;
        #pragma unroll
        for (int n = 0; n < 9; n++) {
            float ox, oy;
            unpack2(acc[n], ox, oy);
            float px = (float)(i + n / 3) + ox;
            float py = (float)(j + n % 3) + oy;
            float fx = floorf(px), fy = floorf(py);
            int qltx = max(min((int)fx, Hp - 1), 0);
            int qlty = max(min((int)fy, Wp - 1), 0);
            int qrbx = max(min((int)fx + 1, Hp - 1), 0);
            int qrby = max(min((int)fy + 1, Wp - 1), 0);
            float pxc = fminf(fmaxf(px, 0.f), (float)(Hp - 1));
            float pyc = fminf(fmaxf(py, 0.f), (float)(Wp - 1));
            float ax = 1.f + (float)qltx - pxc;
            float bx = 1.f - (float)qrbx + pxc;
            float ay = 1.f + (float)qlty - pyc;
            float by = 1.f - (float)qrby + pyc;
            int4 idx;
            idx.x = ((xb130 + qltx) * 130 + qlty) * 64;
            idx.y = ((xb130 + qrbx) * 130 + qrby) * 64;
            idx.z = ((xb130 + qltx) * 130 + qrby) * 64;
            idx.w = ((xb130 + qrbx) * 130 + qlty) * 64;
            float4 wv;
            wv.x = ax * ay;
            wv.y = bx * by;
            wv.z = ax * by;
            wv.w = bx * ay;
            g_midx[n * BHW + P] = idx;      // tap-major layout for coalesced staging
            g_mw[n * BHW + P]   = wv;
        }
    } else if (bid < NB_OFF + NB_PAD) {
        // ---------------- pad + transpose ----------------
        float (*tile)[33] = (float(*)[33])dsm;
        int bp = bid - NB_OFF;
        int b  = bp / 529;
        int p0 = (bp - b * 529) * 32;
        int tx = t & 31;
        int ty = t >> 5;

        #pragma unroll
        for (int cc = ty; cc < 64; cc += 8) {
            int p = p0 + tx;
            float v = 0.f;
            if (p < Hp * Wp) {
                int y = p / Wp, x = p - (p / Wp) * Wp;
                if (y >= 1 && y <= H && x >= 1 && x <= W)
                    v = x0[((b * C + cc) * H + (y - 1)) * W + (x - 1)];
            }
            tile[cc][tx] = v;
        }
        __syncthreads();

        int base = (b * Hp * Wp + p0) * 64;
        for (int e = t; e < 32 * 64; e += 256) {
            int pl = e >> 6, c = e & 63;
            if (p0 + pl < Hp * Wp)
                g_xpad[base + pl * 64 + c] = tile[c][pl];
        }
    } else {
        // ---------------- conv_w reshuffle ----------------
        int idx = (bid - NB_OFF - NB_PAD) * 256 + t;
        if (idx < O * C * N9) {
            int o = idx / (C * N9);
            int c = (idx / N9) % C;
            int n = idx % N9;
            float w = conv_w[idx];
            g_wTn2[(n * C + c) * O + o] = pack2(w, w);
        }
    }
}

// ============================================================================
// k_main: 2-row blocks (256 px x 64 o), 256 threads, smem-staged meta
// (double-buffered, prefetched), tap-major gather + broadcast-W GEMM.
// GEMM: warp = 8 outputs x 256 px; lane = px chunks {lane, lane+32} (8 px).
// Per k-step per warp: 2 LDS.128 X (conflict-free) + 4 uniform LDS.128 W
// (broadcast) + 32 FFMA2.
// ============================================================================
__global__ void __launch_bounds__(256, 2) k_main(float* __restrict__ out) {
    extern __shared__ char dsm[];
    ULL*    ws2    = (ULL*)(dsm + SM_W);
    char*   xoffb  = dsm + SM_X;
    int4*   midx_s = (int4*)(dsm + SM_MIDX);
    float4* mw_s   = (float4*)(dsm + SM_MW);

    int t = threadIdx.x;
    int warp = t >> 5;
    int lane = t & 31;
    int bid = blockIdx.x;             // 256 blocks
    int i2 = bid & 63;                // row pair
    int b  = bid >> 6;
    int pixbase = (b * H + i2 * 2) * W;   // 256 px = 2 rows

    int lg = t & 15;                  // gather: channel quad (c = lg*4)
    int hg = t >> 4;                  // gather: 16-px group (px = hg*16..+15)
    int xorc = lg & 7;

    ULL acc[8][4];
    #pragma unroll
    for (int r = 0; r < 8; r++)
        #pragma unroll
        for (int p = 0; p < 4; p++) acc[r][p] = 0ull;

    const float* xb = g_xpad + lg * 4;

    // prologue: stage meta for tap 0 into buffer 0 (coalesced)
    midx_s[t] = g_midx[pixbase + t];
    mw_s[t]   = g_mw[pixbase + t];
    __syncthreads();

    #pragma unroll 1
    for (int n = 0; n < 9; n++) {
        int cur = n & 1, nxt = cur ^ 1;

        // ---- phase 1: stage W(n), prefetch meta(n+1), gather X(n) ----
        {
            const float4* wsrc = (const float4*)(g_wTn2 + n * 4096);
            float4* wdst = (float4*)(dsm + SM_W);
            #pragma unroll
            for (int k2 = 0; k2 < 8; k2++) wdst[t + k2 * 256] = wsrc[t + k2 * 256];
        }
        if (n < 8) {
            midx_s[nxt * 256 + t] = g_midx[(n + 1) * BHW + pixbase + t];
            mw_s[nxt * 256 + t]   = g_mw[(n + 1) * BHW + pixbase + t];
        }

        #pragma unroll 1
        for (int j = 0; j < 4; j++) {
            float rr[4][4];
            #pragma unroll
            for (int jj = 0; jj < 4; jj++) {
                int px = hg * 16 + j * 4 + jj;
                int4   id = midx_s[cur * 256 + px];
                float4 g  = mw_s[cur * 256 + px];
                float4 v0 = *(const float4*)(xb + id.x);
                float4 v1 = *(const float4*)(xb + id.y);
                float4 v2 = *(const float4*)(xb + id.z);
                float4 v3 = *(const float4*)(xb + id.w);
                rr[jj][0] = g.x * v0.x + g.y * v1.x + g.z * v2.x + g.w * v3.x;
                rr[jj][1] = g.x * v0.y + g.y * v1.y + g.z * v2.y + g.w * v3.y;
                rr[jj][2] = g.x * v0.z + g.y * v1.z + g.z * v2.z + g.w * v3.z;
                rr[jj][3] = g.x * v0.w + g.y * v1.w + g.z * v2.w + g.w * v3.w;
            }
            int chunk = (hg * 4 + j) ^ xorc;       // XOR-swizzled 16B chunk (4 px)
            #pragma unroll
            for (int q = 0; q < 4; q++) {
                *(float4*)(xoffb + (lg * 4 + q) * 1024 + chunk * 16) =
                    make_float4(rr[0][q], rr[1][q], rr[2][q], rr[3][q]);
            }
        }
        __syncthreads();

        // ---- phase 2: GEMM ----
        #pragma unroll 2
        for (int k = 0; k < 64; k++) {
            const char* xrow = xoffb + (k << 10);
            int xk = (k >> 2) & 7;
            ulonglong2 xA = *(const ulonglong2*)(xrow + ((lane ^ xk) << 4));
            ulonglong2 xB = *(const ulonglong2*)(xrow + (((lane + 32) ^ xk) << 4));
            const ULL* wr = ws2 + (k << 6) + (warp << 3);      // warp-uniform
            ulonglong2 w01 = *(const ulonglong2*)(wr + 0);
            ulonglong2 w23 = *(const ulonglong2*)(wr + 2);
            ulonglong2 w45 = *(const ulonglong2*)(wr + 4);
            ulonglong2 w67 = *(const ulonglong2*)(wr + 6);
            acc[0][0] = ffma2(xA.x, w01.x, acc[0][0]);
            acc[0][1] = ffma2(xA.y, w01.x, acc[0][1]);
            acc[0][2] = ffma2(xB.x, w01.x, acc[0][2]);
            acc[0][3] = ffma2(xB.y, w01.x, acc[0][3]);
            acc[1][0] = ffma2(xA.x, w01.y, acc[1][0]);
            acc[1][1] = ffma2(xA.y, w01.y, acc[1][1]);
            acc[1][2] = ffma2(xB.x, w01.y, acc[1][2]);
            acc[1][3] = ffma2(xB.y, w01.y, acc[1][3]);
            acc[2][0] = ffma2(xA.x, w23.x, acc[2][0]);
            acc[2][1] = ffma2(xA.y, w23.x, acc[2][1]);
            acc[2][2] = ffma2(xB.x, w23.x, acc[2][2]);
            acc[2][3] = ffma2(xB.y, w23.x, acc[2][3]);
            acc[3][0] = ffma2(xA.x, w23.y, acc[3][0]);
            acc[3][1] = ffma2(xA.y, w23.y, acc[3][1]);
            acc[3][2] = ffma2(xB.x, w23.y, acc[3][2]);
            acc[3][3] = ffma2(xB.y, w23.y, acc[3][3]);
            acc[4][0] = ffma2(xA.x, w45.x, acc[4][0]);
            acc[4][1] = ffma2(xA.y, w45.x, acc[4][1]);
            acc[4][2] = ffma2(xB.x, w45.x, acc[4][2]);
            acc[4][3] = ffma2(xB.y, w45.x, acc[4][3]);
            acc[5][0] = ffma2(xA.x, w45.y, acc[5][0]);
            acc[5][1] = ffma2(xA.y, w45.y, acc[5][1]);
            acc[5][2] = ffma2(xB.x, w45.y, acc[5][2]);
            acc[5][3] = ffma2(xB.y, w45.y, acc[5][3]);
            acc[6][0] = ffma2(xA.x, w67.x, acc[6][0]);
            acc[6][1] = ffma2(xA.y, w67.x, acc[6][1]);
            acc[6][2] = ffma2(xB.x, w67.x, acc[6][2]);
            acc[6][3] = ffma2(xB.y, w67.x, acc[6][3]);
            acc[7][0] = ffma2(xA.x, w67.y, acc[7][0]);
            acc[7][1] = ffma2(xA.y, w67.y, acc[7][1]);
            acc[7][2] = ffma2(xB.x, w67.y, acc[7][2]);
            acc[7][3] = ffma2(xB.y, w67.y, acc[7][3]);
        }
        __syncthreads();
    }

    // ---- write out: o = warp*8+r; px lane*4..+3 (row i0) and +128 (row i0+1) ----
    float* ob = out + ((b * O + warp * 8) * H + i2 * 2) * W + lane * 4;
    #pragma unroll
    for (int r = 0; r < 8; r++) {
        float4 pA, pB;
        unpack2(acc[r][0], pA.x, pA.y);
        unpack2(acc[r][1], pA.z, pA.w);
        unpack2(acc[r][2], pB.x, pB.y);
        unpack2(acc[r][3], pB.z, pB.w);
        *(float4*)(ob + r * (H * W))     = pA;   // row i0
        *(float4*)(ob + r * (H * W) + W) = pB;   // row i0 + 1
    }
}

// ============================================================================
extern "C" void kernel_launch(void* const* d_in, const int* in_sizes, int n_in,
                              void* d_out, int out_size) {
    const float* x0     = (const float*)d_in[0];
    const float* x1     = (const float*)d_in[1];
    const float* p_w    = (const float*)d_in[2];
    const float* p_b    = (const float*)d_in[3];
    const float* conv_w = (const float*)d_in[4];
    float* out = (float*)d_out;

    cudaFuncSetAttribute(k_main, cudaFuncAttributeMaxDynamicSharedMemorySize, SM_MAIN);

    k_prep<<<NB_OFF + NB_PAD + NB_PW, 256, PREP_SMEM>>>(x0, x1, p_w, p_b, conv_w);
    k_main<<<B * H / 2, 256, SM_MAIN>>>(out);
}